// round 1
// baseline (speedup 1.0000x reference)
#include <cuda_runtime.h>
#include <math.h>

// Problem constants (B=32, H=W=56, C=384, win=7, shift=3, heads=12)
#define NROWS 100352            // B * H * W tokens
#define CDIM  384
#define QKVN  1152
#define HID   1536

// ---------------------------------------------------------------------------
// Scratch (static __device__ arrays; allocation APIs are forbidden)
// ---------------------------------------------------------------------------
__device__ float g_xw [(size_t)NROWS * CDIM];   // LN1 + shifted window-partitioned input
__device__ float g_qkv[(size_t)NROWS * QKVN];   // fused qkv
__device__ float g_ctx[(size_t)NROWS * CDIM];   // attention output (window order)
__device__ float g_x2 [(size_t)NROWS * CDIM];   // post-attention residual (token order)
__device__ float g_y  [(size_t)NROWS * CDIM];   // LN2 output
__device__ float g_h1 [(size_t)NROWS * HID];    // fc1 + gelu output

// Map window-order row r -> token-order row (both the forward shift gather and
// the reverse-shift scatter use the identical (p+3)%56 mapping).
__device__ __forceinline__ int shift_map(int r) {
    int b   = r / 3136;
    int rem = r - b * 3136;
    int w   = rem / 49;
    int n   = rem - w * 49;
    int nr  = n / 7, nc = n - nr * 7;
    int p = (w >> 3) * 7 + nr;
    int q = (w & 7)  * 7 + nc;
    p += 3; if (p >= 56) p -= 56;
    q += 3; if (q >= 56) q -= 56;
    return b * 3136 + p * 56 + q;
}

// ---------------------------------------------------------------------------
// LayerNorm (one block per row of 384). gather=1: output row r (window order)
// reads token shift_map(r)  (fuses roll(-3) + window_partition into LN1).
// ---------------------------------------------------------------------------
__global__ __launch_bounds__(128) void ln_kernel(
    const float* __restrict__ x, const float* __restrict__ gw,
    const float* __restrict__ gb, float* __restrict__ out, int gather)
{
    __shared__ float sh[4], sh2[4], bc[2];
    int r = blockIdx.x;
    int src = gather ? shift_map(r) : r;
    const float* xin = x + (size_t)src * CDIM;
    int t = threadIdx.x;
    float v0 = xin[t], v1 = xin[t + 128], v2 = xin[t + 256];
    float s  = v0 + v1 + v2;
    float ss = v0 * v0 + v1 * v1 + v2 * v2;
#pragma unroll
    for (int o = 16; o > 0; o >>= 1) {
        s  += __shfl_down_sync(0xffffffffu, s,  o);
        ss += __shfl_down_sync(0xffffffffu, ss, o);
    }
    int lane = t & 31, wid = t >> 5;
    if (lane == 0) { sh[wid] = s; sh2[wid] = ss; }
    __syncthreads();
    if (t == 0) {
        float S  = sh[0] + sh[1] + sh[2] + sh[3];
        float SS = sh2[0] + sh2[1] + sh2[2] + sh2[3];
        float mean = S * (1.0f / 384.0f);
        bc[0] = mean;
        bc[1] = rsqrtf(SS * (1.0f / 384.0f) - mean * mean + 1e-5f);
    }
    __syncthreads();
    float mean = bc[0], inv = bc[1];
    float* o = out + (size_t)r * CDIM;
    o[t]       = (v0 - mean) * inv * gw[t]       + gb[t];
    o[t + 128] = (v1 - mean) * inv * gw[t + 128] + gb[t + 128];
    o[t + 256] = (v2 - mean) * inv * gw[t + 256] + gb[t + 256];
}

// ---------------------------------------------------------------------------
// fp32 SGEMM: C[M,N] = A[M,K] @ B[K,N] (+ epilogue). 128x128 tile, Ktile=8,
// 256 threads, 8x8 per thread. M=100352, all dims divide tiles exactly.
// EPI 0: +bias          -> C
// EPI 1: +bias, GELU    -> C
// EPI 2: +bias, scatter row shift_map(r), += res[dest] (proj + window-reverse
//        + roll(+3) + residual, written in token order)
// EPI 3: +bias, += res[r] (fc2 + final residual)
// ---------------------------------------------------------------------------
template<int EPI>
__global__ __launch_bounds__(256) void sgemm128(
    const float* __restrict__ A, const float* __restrict__ B,
    const float* __restrict__ bias, const float* __restrict__ res,
    float* __restrict__ C, int N, int K)
{
    __shared__ float As[8][128];
    __shared__ float Bs[8][128];
    int tid = threadIdx.x;
    int tx = tid & 15, ty = tid >> 4;
    int bM = blockIdx.y * 128, bN = blockIdx.x * 128;

    float acc[8][8];
#pragma unroll
    for (int i = 0; i < 8; i++)
#pragma unroll
        for (int j = 0; j < 8; j++) acc[i][j] = 0.0f;

    int arow = tid >> 1, acol = (tid & 1) * 4;
    int brow = tid >> 5, bcol = (tid & 31) * 4;
    const float* Aptr = A + (size_t)(bM + arow) * K + acol;
    const float* Bptr = B + (size_t)brow * N + bN + bcol;

    for (int k0 = 0; k0 < K; k0 += 8) {
        float4 av = *(const float4*)(Aptr + k0);
        float4 bv = *(const float4*)(Bptr + (size_t)k0 * N);
        As[acol + 0][arow] = av.x;
        As[acol + 1][arow] = av.y;
        As[acol + 2][arow] = av.z;
        As[acol + 3][arow] = av.w;
        *(float4*)&Bs[brow][bcol] = bv;
        __syncthreads();
#pragma unroll
        for (int kk = 0; kk < 8; kk++) {
            float a[8], b[8];
#pragma unroll
            for (int i = 0; i < 8; i++) a[i] = As[kk][ty * 8 + i];
#pragma unroll
            for (int j = 0; j < 8; j++) b[j] = Bs[kk][tx * 8 + j];
#pragma unroll
            for (int i = 0; i < 8; i++)
#pragma unroll
                for (int j = 0; j < 8; j++)
                    acc[i][j] = fmaf(a[i], b[j], acc[i][j]);
        }
        __syncthreads();
    }

    int rm = bM + ty * 8;
    int cn = bN + tx * 8;
#pragma unroll
    for (int i = 0; i < 8; i++) {
        int r  = rm + i;
        int dr = (EPI == 2) ? shift_map(r) : r;
        float* crow = C + (size_t)dr * N + cn;
        const float* rrow = nullptr;
        if (EPI == 2) rrow = res + (size_t)dr * N + cn;
        if (EPI == 3) rrow = res + (size_t)r  * N + cn;
#pragma unroll
        for (int j = 0; j < 8; j++) {
            float v = acc[i][j] + bias[cn + j];
            if (EPI == 1) v = 0.5f * v * (1.0f + erff(v * 0.70710678118654752f));
            if (EPI >= 2) v += rrow[j];
            crow[j] = v;
        }
    }
}

// ---------------------------------------------------------------------------
// Windowed attention: one block per (head, window). N=49, hd=32.
// Bias from rel-pos table and the shifted-window mask computed analytically.
// ---------------------------------------------------------------------------
__global__ __launch_bounds__(256) void attn_kernel(
    const float* __restrict__ qkv, const float* __restrict__ rpb,
    float* __restrict__ ctx)
{
    __shared__ float qs[49][33], ks[49][33], vs[49][33], at[49][50];
    int head = blockIdx.x;
    int w    = blockIdx.y;
    int tid  = threadIdx.x;
    const float scale = 0.17677669529663687f;   // 1/sqrt(32)

    size_t base0 = (size_t)w * 49 * QKVN + head * 32;
    for (int e = tid; e < 49 * 32; e += 256) {
        int n = e >> 5, d = e & 31;
        size_t b = base0 + (size_t)n * QKVN + d;
        qs[n][d] = qkv[b] * scale;
        ks[n][d] = qkv[b + 384];
        vs[n][d] = qkv[b + 768];
    }
    int wloc = w & 63;
    int wh = wloc >> 3, wwi = wloc & 7;
    __syncthreads();

    for (int e = tid; e < 49 * 49; e += 256) {
        int n = e / 49, m = e - n * 49;
        float s = 0.0f;
#pragma unroll
        for (int d = 0; d < 32; d++) s = fmaf(qs[n][d], ks[m][d], s);
        int nr = n / 7, nc = n - nr * 7;
        int mr = m / 7, mc = m - mr * 7;
        s += rpb[((nr - mr + 6) * 13 + (nc - mc + 6)) * 12 + head];
        // shifted-window mask (H=W=56, shift=3): region boundaries at 49 and 53
        int rn = wh * 7 + nr, cn = wwi * 7 + nc;
        int rm = wh * 7 + mr, cm = wwi * 7 + mc;
        int gn = (rn < 49 ? 0 : (rn < 53 ? 1 : 2)) * 3 + (cn < 49 ? 0 : (cn < 53 ? 1 : 2));
        int gm = (rm < 49 ? 0 : (rm < 53 ? 1 : 2)) * 3 + (cm < 49 ? 0 : (cm < 53 ? 1 : 2));
        if (gn != gm) s -= 100.0f;
        at[n][m] = s;
    }
    __syncthreads();

    if (tid < 49) {
        float mx = -1e30f;
        for (int m = 0; m < 49; m++) mx = fmaxf(mx, at[tid][m]);
        float sum = 0.0f;
        for (int m = 0; m < 49; m++) {
            float e2 = expf(at[tid][m] - mx);
            at[tid][m] = e2;
            sum += e2;
        }
        float inv = 1.0f / sum;
        for (int m = 0; m < 49; m++) at[tid][m] *= inv;
    }
    __syncthreads();

    for (int e = tid; e < 49 * 32; e += 256) {
        int n = e >> 5, d = e & 31;
        float s = 0.0f;
#pragma unroll
        for (int m = 0; m < 49; m++) s = fmaf(at[n][m], vs[m][d], s);
        ctx[((size_t)w * 49 + n) * CDIM + head * 32 + d] = s;
    }
}

// ---------------------------------------------------------------------------
// Launch
// ---------------------------------------------------------------------------
extern "C" void kernel_launch(void* const* d_in, const int* in_sizes, int n_in,
                              void* d_out, int out_size)
{
    const float* x     = (const float*)d_in[0];
    const float* n1w   = (const float*)d_in[1];
    const float* n1b   = (const float*)d_in[2];
    const float* qkvw  = (const float*)d_in[3];
    const float* qkvb  = (const float*)d_in[4];
    const float* rpb   = (const float*)d_in[5];
    const float* projw = (const float*)d_in[6];
    const float* projb = (const float*)d_in[7];
    const float* n2w   = (const float*)d_in[8];
    const float* n2b   = (const float*)d_in[9];
    const float* fc1w  = (const float*)d_in[10];
    const float* fc1b  = (const float*)d_in[11];
    const float* fc2w  = (const float*)d_in[12];
    const float* fc2b  = (const float*)d_in[13];
    float* out = (float*)d_out;

    static float *xw = nullptr, *qkv = nullptr, *ctx = nullptr,
                 *x2 = nullptr, *y = nullptr, *h1 = nullptr;
    if (!xw) {
        cudaGetSymbolAddress((void**)&xw,  g_xw);
        cudaGetSymbolAddress((void**)&qkv, g_qkv);
        cudaGetSymbolAddress((void**)&ctx, g_ctx);
        cudaGetSymbolAddress((void**)&x2,  g_x2);
        cudaGetSymbolAddress((void**)&y,   g_y);
        cudaGetSymbolAddress((void**)&h1,  g_h1);
    }

    // 1) LN1 + roll(-3,-3) + window partition (gather)
    ln_kernel<<<NROWS, 128>>>(x, n1w, n1b, xw, 1);
    // 2) fused QKV GEMM: [100352,384] @ [384,1152]
    sgemm128<0><<<dim3(QKVN / 128, NROWS / 128), 256>>>(xw, qkvw, qkvb, nullptr, qkv, QKVN, CDIM);
    // 3) windowed attention per (head, window)
    attn_kernel<<<dim3(12, 2048), 256>>>(qkv, rpb, ctx);
    // 4) proj GEMM + window reverse + roll(+3,+3) + residual (scatter)
    sgemm128<2><<<dim3(CDIM / 128, NROWS / 128), 256>>>(ctx, projw, projb, x, x2, CDIM, CDIM);
    // 5) LN2
    ln_kernel<<<NROWS, 128>>>(x2, n2w, n2b, y, 0);
    // 6) fc1 + GELU (exact erf)
    sgemm128<1><<<dim3(HID / 128, NROWS / 128), 256>>>(y, fc1w, fc1b, nullptr, h1, HID, CDIM);
    // 7) fc2 + final residual
    sgemm128<3><<<dim3(CDIM / 128, NROWS / 128), 256>>>(h1, fc2w, fc2b, x2, out, CDIM, HID);
}

// round 2
// speedup vs baseline: 2.4506x; 2.4506x over previous
#include <cuda_runtime.h>
#include <math.h>

// Problem constants (B=32, H=W=56, C=384, win=7, shift=3, heads=12)
#define NROWS 100352            // B * H * W tokens
#define CDIM  384
#define QKVN  1152
#define HID   1536

// ---------------------------------------------------------------------------
// Scratch (static __device__ arrays; allocation APIs are forbidden)
// ---------------------------------------------------------------------------
__device__ float g_xw [(size_t)NROWS * CDIM];   // LN1 + shifted window-partitioned input
__device__ float g_qkv[(size_t)NROWS * QKVN];   // fused qkv
__device__ float g_ctx[(size_t)NROWS * CDIM];   // attention output (window order)
__device__ float g_x2 [(size_t)NROWS * CDIM];   // post-attention residual (token order)
__device__ float g_y  [(size_t)NROWS * CDIM];   // LN2 output
__device__ float g_h1 [(size_t)NROWS * HID];    // fc1 + gelu output

// Map window-order row r -> token-order row (both the forward shift gather and
// the reverse-shift scatter use the identical (p+3)%56 mapping).
__device__ __forceinline__ int shift_map(int r) {
    int b   = r / 3136;
    int rem = r - b * 3136;
    int w   = rem / 49;
    int n   = rem - w * 49;
    int nr  = n / 7, nc = n - nr * 7;
    int p = (w >> 3) * 7 + nr;
    int q = (w & 7)  * 7 + nc;
    p += 3; if (p >= 56) p -= 56;
    q += 3; if (q >= 56) q -= 56;
    return b * 3136 + p * 56 + q;
}

__device__ __forceinline__ float to_tf32(float x) {
    unsigned u;
    asm("cvt.rna.tf32.f32 %0, %1;" : "=r"(u) : "f"(x));
    return __uint_as_float(u);
}

__device__ __forceinline__ void mma_tf32(float* d, const unsigned* a, const unsigned* b) {
    asm volatile(
        "mma.sync.aligned.m16n8k8.row.col.f32.tf32.tf32.f32 "
        "{%0,%1,%2,%3}, {%4,%5,%6,%7}, {%8,%9}, {%0,%1,%2,%3};\n"
        : "+f"(d[0]), "+f"(d[1]), "+f"(d[2]), "+f"(d[3])
        : "r"(a[0]), "r"(a[1]), "r"(a[2]), "r"(a[3]), "r"(b[0]), "r"(b[1]));
}

// ---------------------------------------------------------------------------
// LayerNorm (one block per row of 384). gather=1: output row r (window order)
// reads token shift_map(r)  (fuses roll(-3) + window_partition into LN1).
// ---------------------------------------------------------------------------
__global__ __launch_bounds__(128) void ln_kernel(
    const float* __restrict__ x, const float* __restrict__ gw,
    const float* __restrict__ gb, float* __restrict__ out, int gather)
{
    __shared__ float sh[4], sh2[4], bc[2];
    int r = blockIdx.x;
    int src = gather ? shift_map(r) : r;
    const float* xin = x + (size_t)src * CDIM;
    int t = threadIdx.x;
    float v0 = xin[t], v1 = xin[t + 128], v2 = xin[t + 256];
    float s  = v0 + v1 + v2;
    float ss = v0 * v0 + v1 * v1 + v2 * v2;
#pragma unroll
    for (int o = 16; o > 0; o >>= 1) {
        s  += __shfl_down_sync(0xffffffffu, s,  o);
        ss += __shfl_down_sync(0xffffffffu, ss, o);
    }
    int lane = t & 31, wid = t >> 5;
    if (lane == 0) { sh[wid] = s; sh2[wid] = ss; }
    __syncthreads();
    if (t == 0) {
        float S  = sh[0] + sh[1] + sh[2] + sh[3];
        float SS = sh2[0] + sh2[1] + sh2[2] + sh2[3];
        float mean = S * (1.0f / 384.0f);
        bc[0] = mean;
        bc[1] = rsqrtf(SS * (1.0f / 384.0f) - mean * mean + 1e-5f);
    }
    __syncthreads();
    float mean = bc[0], inv = bc[1];
    float* o = out + (size_t)r * CDIM;
    o[t]       = (v0 - mean) * inv * gw[t]       + gb[t];
    o[t + 128] = (v1 - mean) * inv * gw[t + 128] + gb[t + 128];
    o[t + 256] = (v2 - mean) * inv * gw[t + 256] + gb[t + 256];
}

// ---------------------------------------------------------------------------
// TF32 tensor-core GEMM: C[M,N] = A[M,K] @ B[K,N] (+ epilogue).
// 128x128 CTA tile, BK=16, 8 warps in 2x4 grid, 64x32 warp tile
// (4x4 grid of m16n8k8 mma). Double-buffered smem, register-staged prefetch.
// Smem layouts chosen conflict-free for fragment reads:
//   As[buf][m][k]: stride 20  -> read bank (20m+k)%32 covers all 32 banks
//   Bs[buf][k][n]: stride 136 -> read bank (8k+n)%32  covers all 32 banks
// EPI 0: +bias          -> C
// EPI 1: +bias, GELU    -> C
// EPI 2: +bias, scatter row shift_map(r), += res[dest]  (proj epilogue)
// EPI 3: +bias, += res[r]                               (fc2 epilogue)
// ---------------------------------------------------------------------------
template<int EPI>
__global__ __launch_bounds__(256) void tgemm(
    const float* __restrict__ A, const float* __restrict__ B,
    const float* __restrict__ bias, const float* __restrict__ res,
    float* __restrict__ C, int N, int K)
{
    __shared__ float As[2][128][20];
    __shared__ float Bs[2][16][136];

    int tid  = threadIdx.x;
    int warp = tid >> 5, lane = tid & 31;
    int wm = warp >> 2, wn = warp & 3;       // 2 x 4 warp grid
    int gr = lane >> 2, tig = lane & 3;      // mma fragment coords
    int bM = blockIdx.y * 128, bN = blockIdx.x * 128;

    // staging maps
    int mA  = tid >> 2;          // 0..63 (and +64)
    int kqA = (tid & 3) * 4;     // 0,4,8,12
    int kB  = tid >> 5;          // 0..7 (and +8)
    int nqB = (tid & 31) * 4;    // 0..124

    const float* Ap0 = A + (size_t)(bM + mA)      * K + kqA;
    const float* Ap1 = A + (size_t)(bM + mA + 64) * K + kqA;

    float acc[4][4][4];
#pragma unroll
    for (int i = 0; i < 4; i++)
#pragma unroll
        for (int j = 0; j < 4; j++)
#pragma unroll
            for (int r = 0; r < 4; r++) acc[i][j][r] = 0.0f;

    float4 av0, av1, bv0, bv1;

    auto load_tiles = [&](int kt) {
        av0 = *(const float4*)(Ap0 + kt * 16);
        av1 = *(const float4*)(Ap1 + kt * 16);
        bv0 = *(const float4*)(B + (size_t)(kt * 16 + kB)     * N + bN + nqB);
        bv1 = *(const float4*)(B + (size_t)(kt * 16 + kB + 8) * N + bN + nqB);
    };
    auto store_tiles = [&](int buf) {
        float4 t;
        t.x = to_tf32(av0.x); t.y = to_tf32(av0.y); t.z = to_tf32(av0.z); t.w = to_tf32(av0.w);
        *(float4*)&As[buf][mA][kqA] = t;
        t.x = to_tf32(av1.x); t.y = to_tf32(av1.y); t.z = to_tf32(av1.z); t.w = to_tf32(av1.w);
        *(float4*)&As[buf][mA + 64][kqA] = t;
        t.x = to_tf32(bv0.x); t.y = to_tf32(bv0.y); t.z = to_tf32(bv0.z); t.w = to_tf32(bv0.w);
        *(float4*)&Bs[buf][kB][nqB] = t;
        t.x = to_tf32(bv1.x); t.y = to_tf32(bv1.y); t.z = to_tf32(bv1.z); t.w = to_tf32(bv1.w);
        *(float4*)&Bs[buf][kB + 8][nqB] = t;
    };

    int KT = K >> 4;
    load_tiles(0);
    store_tiles(0);
    __syncthreads();

    for (int kt = 0; kt < KT; kt++) {
        int cur = kt & 1;
        if (kt + 1 < KT) load_tiles(kt + 1);

#pragma unroll
        for (int kk = 0; kk < 2; kk++) {
            int k0 = kk * 8;
            unsigned a[4][4], b[4][2];
#pragma unroll
            for (int mt = 0; mt < 4; mt++) {
                int m = wm * 64 + mt * 16 + gr;
                a[mt][0] = __float_as_uint(As[cur][m    ][k0 + tig]);
                a[mt][1] = __float_as_uint(As[cur][m + 8][k0 + tig]);
                a[mt][2] = __float_as_uint(As[cur][m    ][k0 + tig + 4]);
                a[mt][3] = __float_as_uint(As[cur][m + 8][k0 + tig + 4]);
            }
#pragma unroll
            for (int nt = 0; nt < 4; nt++) {
                int n = wn * 32 + nt * 8 + gr;
                b[nt][0] = __float_as_uint(Bs[cur][k0 + tig    ][n]);
                b[nt][1] = __float_as_uint(Bs[cur][k0 + tig + 4][n]);
            }
#pragma unroll
            for (int mt = 0; mt < 4; mt++)
#pragma unroll
                for (int nt = 0; nt < 4; nt++)
                    mma_tf32(acc[mt][nt], a[mt], b[nt]);
        }

        if (kt + 1 < KT) store_tiles(cur ^ 1);
        __syncthreads();
    }

    // Epilogue
#pragma unroll
    for (int mt = 0; mt < 4; mt++) {
        int r0 = bM + wm * 64 + mt * 16 + gr;
        int r1 = r0 + 8;
        int d0 = (EPI == 2) ? shift_map(r0) : r0;
        int d1 = (EPI == 2) ? shift_map(r1) : r1;
#pragma unroll
        for (int nt = 0; nt < 4; nt++) {
            int c0 = bN + wn * 32 + nt * 8 + tig * 2;
            float bb0 = bias[c0], bb1 = bias[c0 + 1];
            float v00 = acc[mt][nt][0] + bb0;
            float v01 = acc[mt][nt][1] + bb1;
            float v10 = acc[mt][nt][2] + bb0;
            float v11 = acc[mt][nt][3] + bb1;
            if (EPI == 1) {
                v00 = 0.5f * v00 * (1.0f + erff(v00 * 0.70710678118654752f));
                v01 = 0.5f * v01 * (1.0f + erff(v01 * 0.70710678118654752f));
                v10 = 0.5f * v10 * (1.0f + erff(v10 * 0.70710678118654752f));
                v11 = 0.5f * v11 * (1.0f + erff(v11 * 0.70710678118654752f));
            }
            if (EPI >= 2) {
                const float2 r0v = *(const float2*)(res + (size_t)d0 * N + c0);
                const float2 r1v = *(const float2*)(res + (size_t)d1 * N + c0);
                v00 += r0v.x; v01 += r0v.y;
                v10 += r1v.x; v11 += r1v.y;
            }
            *(float2*)(C + (size_t)d0 * N + c0) = make_float2(v00, v01);
            *(float2*)(C + (size_t)d1 * N + c0) = make_float2(v10, v11);
        }
    }
}

// ---------------------------------------------------------------------------
// Windowed attention: one block per (head, window). N=49, hd=32.
// Bias from rel-pos table and the shifted-window mask computed analytically.
// ---------------------------------------------------------------------------
__global__ __launch_bounds__(256) void attn_kernel(
    const float* __restrict__ qkv, const float* __restrict__ rpb,
    float* __restrict__ ctx)
{
    __shared__ float qs[49][33], ks[49][33], vs[49][33], at[49][50];
    int head = blockIdx.x;
    int w    = blockIdx.y;
    int tid  = threadIdx.x;
    const float scale = 0.17677669529663687f;   // 1/sqrt(32)

    size_t base0 = (size_t)w * 49 * QKVN + head * 32;
    for (int e = tid; e < 49 * 32; e += 256) {
        int n = e >> 5, d = e & 31;
        size_t b = base0 + (size_t)n * QKVN + d;
        qs[n][d] = qkv[b] * scale;
        ks[n][d] = qkv[b + 384];
        vs[n][d] = qkv[b + 768];
    }
    int wloc = w & 63;
    int wh = wloc >> 3, wwi = wloc & 7;
    __syncthreads();

    for (int e = tid; e < 49 * 49; e += 256) {
        int n = e / 49, m = e - n * 49;
        float s = 0.0f;
#pragma unroll
        for (int d = 0; d < 32; d++) s = fmaf(qs[n][d], ks[m][d], s);
        int nr = n / 7, nc = n - nr * 7;
        int mr = m / 7, mc = m - mr * 7;
        s += rpb[((nr - mr + 6) * 13 + (nc - mc + 6)) * 12 + head];
        // shifted-window mask (H=W=56, shift=3): region boundaries at 49 and 53
        int rn = wh * 7 + nr, cn = wwi * 7 + nc;
        int rm = wh * 7 + mr, cm = wwi * 7 + mc;
        int gn = (rn < 49 ? 0 : (rn < 53 ? 1 : 2)) * 3 + (cn < 49 ? 0 : (cn < 53 ? 1 : 2));
        int gm = (rm < 49 ? 0 : (rm < 53 ? 1 : 2)) * 3 + (cm < 49 ? 0 : (cm < 53 ? 1 : 2));
        if (gn != gm) s -= 100.0f;
        at[n][m] = s;
    }
    __syncthreads();

    if (tid < 49) {
        float mx = -1e30f;
        for (int m = 0; m < 49; m++) mx = fmaxf(mx, at[tid][m]);
        float sum = 0.0f;
        for (int m = 0; m < 49; m++) {
            float e2 = expf(at[tid][m] - mx);
            at[tid][m] = e2;
            sum += e2;
        }
        float inv = 1.0f / sum;
        for (int m = 0; m < 49; m++) at[tid][m] *= inv;
    }
    __syncthreads();

    for (int e = tid; e < 49 * 32; e += 256) {
        int n = e >> 5, d = e & 31;
        float s = 0.0f;
#pragma unroll
        for (int m = 0; m < 49; m++) s = fmaf(at[n][m], vs[m][d], s);
        ctx[((size_t)w * 49 + n) * CDIM + head * 32 + d] = s;
    }
}

// ---------------------------------------------------------------------------
// Launch
// ---------------------------------------------------------------------------
extern "C" void kernel_launch(void* const* d_in, const int* in_sizes, int n_in,
                              void* d_out, int out_size)
{
    const float* x     = (const float*)d_in[0];
    const float* n1w   = (const float*)d_in[1];
    const float* n1b   = (const float*)d_in[2];
    const float* qkvw  = (const float*)d_in[3];
    const float* qkvb  = (const float*)d_in[4];
    const float* rpb   = (const float*)d_in[5];
    const float* projw = (const float*)d_in[6];
    const float* projb = (const float*)d_in[7];
    const float* n2w   = (const float*)d_in[8];
    const float* n2b   = (const float*)d_in[9];
    const float* fc1w  = (const float*)d_in[10];
    const float* fc1b  = (const float*)d_in[11];
    const float* fc2w  = (const float*)d_in[12];
    const float* fc2b  = (const float*)d_in[13];
    float* out = (float*)d_out;

    static float *xw = nullptr, *qkv = nullptr, *ctx = nullptr,
                 *x2 = nullptr, *y = nullptr, *h1 = nullptr;
    if (!xw) {
        cudaGetSymbolAddress((void**)&xw,  g_xw);
        cudaGetSymbolAddress((void**)&qkv, g_qkv);
        cudaGetSymbolAddress((void**)&ctx, g_ctx);
        cudaGetSymbolAddress((void**)&x2,  g_x2);
        cudaGetSymbolAddress((void**)&y,   g_y);
        cudaGetSymbolAddress((void**)&h1,  g_h1);
    }

    // 1) LN1 + roll(-3,-3) + window partition (gather)
    ln_kernel<<<NROWS, 128>>>(x, n1w, n1b, xw, 1);
    // 2) fused QKV GEMM: [100352,384] @ [384,1152]
    tgemm<0><<<dim3(QKVN / 128, NROWS / 128), 256>>>(xw, qkvw, qkvb, nullptr, qkv, QKVN, CDIM);
    // 3) windowed attention per (head, window)
    attn_kernel<<<dim3(12, 2048), 256>>>(qkv, rpb, ctx);
    // 4) proj GEMM + window reverse + roll(+3,+3) + residual (scatter)
    tgemm<2><<<dim3(CDIM / 128, NROWS / 128), 256>>>(ctx, projw, projb, x, x2, CDIM, CDIM);
    // 5) LN2
    ln_kernel<<<NROWS, 128>>>(x2, n2w, n2b, y, 0);
    // 6) fc1 + GELU (exact erf)
    tgemm<1><<<dim3(HID / 128, NROWS / 128), 256>>>(y, fc1w, fc1b, nullptr, h1, HID, CDIM);
    // 7) fc2 + final residual
    tgemm<3><<<dim3(CDIM / 128, NROWS / 128), 256>>>(h1, fc2w, fc2b, x2, out, CDIM, HID);
}